// round 1
// baseline (speedup 1.0000x reference)
#include <cuda_runtime.h>

// Per-sample 2-layer MLP:
//   h = relu(x[b,:] @ w1[b,:,:] + b1[b,:])   (D=128 -> H=256)
//   out = h @ w2[b,:,:] + b2[b,:]            (H=256 -> C=64)
// B=4096 samples. Pure HBM-streaming problem (~774 MB, zero weight reuse).

#define B_DIM 4096
#define D_DIM 128
#define H_DIM 256
#define C_DIM 64

__global__ void __launch_bounds__(256, 8) mlp_per_sample_kernel(
    const float* __restrict__ x,
    const float* __restrict__ w1,
    const float* __restrict__ b1,
    const float* __restrict__ w2,
    const float* __restrict__ b2,
    float* __restrict__ out)
{
    const int b   = blockIdx.x;
    const int tid = threadIdx.x;

    __shared__ float  x_s[D_DIM];
    __shared__ float  h_s[H_DIM];
    __shared__ float4 part[256];

    // ---- stage x[b,:] ----
    if (tid < D_DIM) x_s[tid] = x[(size_t)b * D_DIM + tid];
    __syncthreads();

    // ================= GEMV1: h[j] = sum_d x[d] * w1[d, j] =================
    // w1[b] viewed as float4[D_DIM][H_DIM/4]. 64 column-groups of 4 cols.
    // Thread = (dchunk in 0..3, g in 0..63). Each thread: 32 float4 LDGs,
    // warp-contiguous -> fully coalesced 1024B rows.
    {
        const float4* w1v = reinterpret_cast<const float4*>(
            w1 + (size_t)b * D_DIM * H_DIM);
        const int g      = tid & 63;
        const int dchunk = tid >> 6;
        const int dbase  = dchunk * 32;

        float4 acc = make_float4(0.f, 0.f, 0.f, 0.f);
        #pragma unroll
        for (int i = 0; i < 32; ++i) {
            const int d = dbase + i;
            const float  xv = x_s[d];
            const float4 w  = w1v[d * (H_DIM / 4) + g];
            acc.x = fmaf(xv, w.x, acc.x);
            acc.y = fmaf(xv, w.y, acc.y);
            acc.z = fmaf(xv, w.z, acc.z);
            acc.w = fmaf(xv, w.w, acc.w);
        }
        part[tid] = acc;   // index == dchunk*64 + g
    }
    __syncthreads();

    if (tid < 64) {
        float4 s0 = part[tid];
        float4 s1 = part[64 + tid];
        float4 s2 = part[128 + tid];
        float4 s3 = part[192 + tid];
        float4 bb = reinterpret_cast<const float4*>(b1 + (size_t)b * H_DIM)[tid];
        float4 h4;
        h4.x = fmaxf(s0.x + s1.x + s2.x + s3.x + bb.x, 0.f);
        h4.y = fmaxf(s0.y + s1.y + s2.y + s3.y + bb.y, 0.f);
        h4.z = fmaxf(s0.z + s1.z + s2.z + s3.z + bb.z, 0.f);
        h4.w = fmaxf(s0.w + s1.w + s2.w + s3.w + bb.w, 0.f);
        reinterpret_cast<float4*>(h_s)[tid] = h4;
    }
    __syncthreads();

    // ================= GEMV2: out[c] = sum_j h[j] * w2[j, c] ===============
    // w2[b] viewed as float4[H_DIM][C_DIM/4]. 16 column-groups of 4 cols.
    // Thread = (jchunk in 0..15, cg in 0..15). 16 float4 LDGs per thread,
    // coalesced 256B row segments.
    {
        const float4* w2v = reinterpret_cast<const float4*>(
            w2 + (size_t)b * H_DIM * C_DIM);
        const int cg     = tid & 15;
        const int jchunk = tid >> 4;
        const int jbase  = jchunk * 16;

        float4 acc = make_float4(0.f, 0.f, 0.f, 0.f);
        #pragma unroll
        for (int i = 0; i < 16; ++i) {
            const int j = jbase + i;
            const float  hv = h_s[j];
            const float4 w  = w2v[j * (C_DIM / 4) + cg];
            acc.x = fmaf(hv, w.x, acc.x);
            acc.y = fmaf(hv, w.y, acc.y);
            acc.z = fmaf(hv, w.z, acc.z);
            acc.w = fmaf(hv, w.w, acc.w);
        }
        part[tid] = acc;   // index == jchunk*16 + cg
    }
    __syncthreads();

    if (tid < 16) {
        float4 s = part[tid];
        #pragma unroll
        for (int k = 1; k < 16; ++k) {
            float4 p = part[k * 16 + tid];
            s.x += p.x; s.y += p.y; s.z += p.z; s.w += p.w;
        }
        float4 bb = reinterpret_cast<const float4*>(b2 + (size_t)b * C_DIM)[tid];
        s.x += bb.x; s.y += bb.y; s.z += bb.z; s.w += bb.w;
        reinterpret_cast<float4*>(out + (size_t)b * C_DIM)[tid] = s;
    }
}

extern "C" void kernel_launch(void* const* d_in, const int* in_sizes, int n_in,
                              void* d_out, int out_size)
{
    const float* x  = (const float*)d_in[0];
    const float* w1 = (const float*)d_in[1];
    const float* b1 = (const float*)d_in[2];
    const float* w2 = (const float*)d_in[3];
    const float* b2 = (const float*)d_in[4];
    float* out = (float*)d_out;

    mlp_per_sample_kernel<<<B_DIM, 256>>>(x, w1, b1, w2, b2, out);
}

// round 2
// speedup vs baseline: 1.0542x; 1.0542x over previous
#include <cuda_runtime.h>

// Per-sample 2-layer MLP, 2 samples per CTA:
//   h = relu(x[b,:] @ w1[b,:,:] + b1[b,:])   (D=128 -> H=256)
//   out = h @ w2[b,:,:] + b2[b,:]            (H=256 -> C=64)
// B=4096 samples, grid = 2048 CTAs x 256 threads.
// Half-block (128 threads) per sample -> 64 float4 LDGs/thread in GEMV1,
// 32 in GEMV2: deep MLP, barriers amortized over 2 samples.

#define B_DIM 4096
#define D_DIM 128
#define H_DIM 256
#define C_DIM 64

__global__ void __launch_bounds__(256, 6) mlp_2samp_kernel(
    const float* __restrict__ x,
    const float* __restrict__ w1,
    const float* __restrict__ b1,
    const float* __restrict__ w2,
    const float* __restrict__ b2,
    float* __restrict__ out)
{
    const int tid = threadIdx.x;
    const int s   = tid >> 7;        // 0 or 1: which sample this half-block owns
    const int l   = tid & 127;       // lane within half-block
    const int b   = blockIdx.x * 2 + s;

    __shared__ float  x_s[2][D_DIM];
    __shared__ float  h_s[2][H_DIM];
    __shared__ float4 part[2][128];

    // ---- stage x for both samples ----
    if (l < D_DIM) x_s[s][l] = x[(size_t)b * D_DIM + l];
    __syncthreads();

    // ================= GEMV1: h[j] = sum_d x[d] * w1[d, j] =================
    // w1[b] as float4[128][64]. Thread: (dchunk = l>>6 in 0..1, g = l&63).
    // 64 float4 loads per thread, warp-contiguous 1024B rows.
    {
        const float4* w1v = reinterpret_cast<const float4*>(
            w1 + (size_t)b * D_DIM * H_DIM);
        const int g     = l & 63;
        const int dbase = (l >> 6) * 64;

        float4 acc = make_float4(0.f, 0.f, 0.f, 0.f);
        #pragma unroll
        for (int i = 0; i < 64; ++i) {
            const int d = dbase + i;
            const float  xv = x_s[s][d];
            const float4 w  = __ldcs(&w1v[d * (H_DIM / 4) + g]);
            acc.x = fmaf(xv, w.x, acc.x);
            acc.y = fmaf(xv, w.y, acc.y);
            acc.z = fmaf(xv, w.z, acc.z);
            acc.w = fmaf(xv, w.w, acc.w);
        }
        part[s][l] = acc;
    }
    __syncthreads();

    // reduce 2 partials per column group, add bias, ReLU
    if (l < 64) {
        float4 s0 = part[s][l];
        float4 s1 = part[s][64 + l];
        float4 bb = reinterpret_cast<const float4*>(b1 + (size_t)b * H_DIM)[l];
        float4 h4;
        h4.x = fmaxf(s0.x + s1.x + bb.x, 0.f);
        h4.y = fmaxf(s0.y + s1.y + bb.y, 0.f);
        h4.z = fmaxf(s0.z + s1.z + bb.z, 0.f);
        h4.w = fmaxf(s0.w + s1.w + bb.w, 0.f);
        reinterpret_cast<float4*>(h_s[s])[l] = h4;
    }
    __syncthreads();

    // ================= GEMV2: out[c] = sum_j h[j] * w2[j, c] ===============
    // w2[b] as float4[256][16]. Thread: (jchunk = l>>4 in 0..7, cg = l&15).
    // 32 float4 loads per thread, coalesced 256B row segments.
    {
        const float4* w2v = reinterpret_cast<const float4*>(
            w2 + (size_t)b * H_DIM * C_DIM);
        const int cg    = l & 15;
        const int jbase = (l >> 4) * 32;

        float4 acc = make_float4(0.f, 0.f, 0.f, 0.f);
        #pragma unroll
        for (int i = 0; i < 32; ++i) {
            const int j = jbase + i;
            const float  hv = h_s[s][j];
            const float4 w  = __ldcs(&w2v[j * (C_DIM / 4) + cg]);
            acc.x = fmaf(hv, w.x, acc.x);
            acc.y = fmaf(hv, w.y, acc.y);
            acc.z = fmaf(hv, w.z, acc.z);
            acc.w = fmaf(hv, w.w, acc.w);
        }
        part[s][l] = acc;
    }
    __syncthreads();

    // reduce 8 partials per output group, add bias, streaming store
    if (l < 16) {
        float4 acc = part[s][l];
        #pragma unroll
        for (int k = 1; k < 8; ++k) {
            float4 p = part[s][k * 16 + l];
            acc.x += p.x; acc.y += p.y; acc.z += p.z; acc.w += p.w;
        }
        float4 bb = reinterpret_cast<const float4*>(b2 + (size_t)b * C_DIM)[l];
        acc.x += bb.x; acc.y += bb.y; acc.z += bb.z; acc.w += bb.w;
        __stcs(reinterpret_cast<float4*>(out + (size_t)b * C_DIM) + l, acc);
    }
}

extern "C" void kernel_launch(void* const* d_in, const int* in_sizes, int n_in,
                              void* d_out, int out_size)
{
    const float* x  = (const float*)d_in[0];
    const float* w1 = (const float*)d_in[1];
    const float* b1 = (const float*)d_in[2];
    const float* w2 = (const float*)d_in[3];
    const float* b2 = (const float*)d_in[4];
    float* out = (float*)d_out;

    mlp_2samp_kernel<<<B_DIM / 2, 256>>>(x, w1, b1, w2, b2, out);
}